// round 3
// baseline (speedup 1.0000x reference)
#include <cuda_runtime.h>
#include <cuda_bf16.h>

// ---------------- static scratch (no allocations allowed) ----------------
#define CAP_N 2000000
#define CAP_S 4096

__device__ int   g_node_off[1025];
__device__ int   g_hist[CAP_S];
__device__ int   g_start[CAP_S + 1];
__device__ int   g_cursor[CAP_S];
__device__ int   g_idx[CAP_N];
__device__ float g_inv[CAP_N];

// ---------------- helpers ----------------
__device__ __forceinline__ int find_graph(const int* s_off, int B, int node) {
    int lo = 0, hi = B;
    while (hi - lo > 1) {
        int mid = (lo + hi) >> 1;
        if (s_off[mid] <= node) lo = mid; else hi = mid;
    }
    return lo;
}

__global__ void k_prefix(const int* __restrict__ bn, int B) {
    if (threadIdx.x == 0) {
        int acc = 0;
        g_node_off[0] = 0;
        for (int i = 0; i < B; ++i) { acc += bn[i]; g_node_off[i + 1] = acc; }
    }
}

__global__ void k_clear(int S) {
    int i = blockIdx.x * blockDim.x + threadIdx.x;
    if (i < S) g_hist[i] = 0;
}

// Pass A1: per-segment histogram
__global__ void __launch_bounds__(256) k_hist(const int* __restrict__ xy,
                                              int N, int G, int B) {
    extern __shared__ int s_off[];
    for (int i = threadIdx.x; i <= B; i += blockDim.x) s_off[i] = g_node_off[i];
    __syncthreads();
    int n = blockIdx.x * blockDim.x + threadIdx.x;
    if (n < N) {
        int r = xy[3 * n], c = xy[3 * n + 1];
        int g = find_graph(s_off, B, n);
        atomicAdd(&g_hist[(g * G + r) * G + c], 1);
    }
}

// Pass A2: exclusive scan of S<=4096 counters (single 1024-thread CTA)
__global__ void k_scan(int S) {
    __shared__ int s_part[1024];
    int t = threadIdx.x;
    int per = (S + 1023) / 1024;
    int base = t * per;
    int sum = 0;
    for (int j = 0; j < per; ++j) {
        int i = base + j;
        if (i < S) sum += g_hist[i];
    }
    s_part[t] = sum;
    __syncthreads();
    for (int off = 1; off < 1024; off <<= 1) {
        int v = (t >= off) ? s_part[t - off] : 0;
        __syncthreads();
        s_part[t] += v;
        __syncthreads();
    }
    int excl = s_part[t] - sum;
    for (int j = 0; j < per; ++j) {
        int i = base + j;
        if (i < S) {
            g_start[i]  = excl;
            g_cursor[i] = excl;
            excl += g_hist[i];
        }
    }
    if (t == 1023) g_start[S] = s_part[1023];
}

// Pass A3: scatter node index + weight into segment-sorted order
__global__ void __launch_bounds__(256) k_scatter(const int* __restrict__ xy,
                                                 int N, int G, int B) {
    extern __shared__ int s_off[];
    for (int i = threadIdx.x; i <= B; i += blockDim.x) s_off[i] = g_node_off[i];
    __syncthreads();
    int n = blockIdx.x * blockDim.x + threadIdx.x;
    if (n < N) {
        int r = xy[3 * n], c = xy[3 * n + 1], dv = xy[3 * n + 2];
        int g = find_graph(s_off, B, n);
        int seg = (g * G + r) * G + c;
        int pos = atomicAdd(&g_cursor[seg], 1);
        g_idx[pos] = n;
        g_inv[pos] = 1.0f / (float)dv;
    }
}

// Pass B: one CTA per segment, register-resident accumulation, zero atomics.
// 256 threads = 32 float4 slots x 8 node groups (D == 128).
__global__ void __launch_bounds__(256) k_reduce(const float* __restrict__ feat,
                                                float* __restrict__ out) {
    const int D = 128;
    const int seg   = blockIdx.x;
    const int start = g_start[seg];
    const int end   = g_start[seg + 1];
    const int t     = threadIdx.x;
    const int slot  = t & 31;
    const int grp   = t >> 5;

    float4 a0 = make_float4(0.f, 0.f, 0.f, 0.f);
    float4 a1 = make_float4(0.f, 0.f, 0.f, 0.f);

    int i = start + grp;
    for (; i + 8 < end; i += 16) {
        int   n0 = __ldg(&g_idx[i]);
        int   n1 = __ldg(&g_idx[i + 8]);
        float w0 = __ldg(&g_inv[i]);
        float w1 = __ldg(&g_inv[i + 8]);
        float4 v0 = __ldg(reinterpret_cast<const float4*>(feat + (size_t)n0 * D) + slot);
        float4 v1 = __ldg(reinterpret_cast<const float4*>(feat + (size_t)n1 * D) + slot);
        a0.x += v0.x * w0; a0.y += v0.y * w0; a0.z += v0.z * w0; a0.w += v0.w * w0;
        a1.x += v1.x * w1; a1.y += v1.y * w1; a1.z += v1.z * w1; a1.w += v1.w * w1;
    }
    for (; i < end; i += 8) {
        int   n0 = __ldg(&g_idx[i]);
        float w0 = __ldg(&g_inv[i]);
        float4 v0 = __ldg(reinterpret_cast<const float4*>(feat + (size_t)n0 * D) + slot);
        a0.x += v0.x * w0; a0.y += v0.y * w0; a0.z += v0.z * w0; a0.w += v0.w * w0;
    }
    a0.x += a1.x; a0.y += a1.y; a0.z += a1.z; a0.w += a1.w;

    __shared__ float s_red[8][128];
    s_red[grp][slot * 4 + 0] = a0.x;
    s_red[grp][slot * 4 + 1] = a0.y;
    s_red[grp][slot * 4 + 2] = a0.z;
    s_red[grp][slot * 4 + 3] = a0.w;
    __syncthreads();

    if (t < 128) {
        float s = 0.f;
        #pragma unroll
        for (int g = 0; g < 8; ++g) s += s_red[g][t];
        out[(size_t)seg * D + t] = s;
    }
}

// ---------------- fallback path (round-2 kernel) ----------------
__global__ void __launch_bounds__(256) spp_pool_fallback(
    const float* __restrict__ feat, const int* __restrict__ xy,
    float* __restrict__ out, int N, int D, int G, int B)
{
    extern __shared__ int s_off[];
    for (int i = threadIdx.x; i <= B; i += blockDim.x) s_off[i] = g_node_off[i];
    __syncthreads();

    const int lane   = threadIdx.x & 31;
    const int warp   = (blockIdx.x * blockDim.x + threadIdx.x) >> 5;
    const int nwarps = (gridDim.x * blockDim.x) >> 5;

    for (long long base = (long long)warp * 32; base < N;
         base += (long long)nwarps * 32) {
        long long mynode = base + lane;
        int nd = (mynode < N) ? (int)mynode : (N - 1);
        const int r  = __ldg(&xy[3 * nd + 0]);
        const int c  = __ldg(&xy[3 * nd + 1]);
        const int dv = __ldg(&xy[3 * nd + 2]);
        int g = find_graph(s_off, B, nd);
        const int   myseg = (g * G + r) * G + c;
        const float myinv = 1.0f / (float)dv;
        const int cnt = (N - base >= 32) ? 32 : (int)(N - base);

        for (int j = 0; j < cnt; ++j) {
            const int   seg = __shfl_sync(0xffffffffu, myseg, j);
            const float inv = __shfl_sync(0xffffffffu, myinv, j);
            const float* src = feat + ((size_t)(base + j)) * D;
            for (int d4 = lane; d4 * 4 < D; d4 += 32) {
                float4 v = __ldg(reinterpret_cast<const float4*>(src) + d4);
                v.x *= inv; v.y *= inv; v.z *= inv; v.w *= inv;
                float* dst = out + (size_t)seg * D + d4 * 4;
                asm volatile("red.global.add.v4.f32 [%0], {%1, %2, %3, %4};"
                             :: "l"(dst), "f"(v.x), "f"(v.y), "f"(v.z), "f"(v.w)
                             : "memory");
            }
        }
    }
}

extern "C" void kernel_launch(void* const* d_in, const int* in_sizes, int n_in,
                              void* d_out, int out_size) {
    const float* feat = (const float*)d_in[0];
    const int*   xy   = (const int*)d_in[1];
    const int*   bn   = (const int*)d_in[2];
    float*       out  = (float*)d_out;

    const int B = in_sizes[2];
    const int N = in_sizes[1] / 3;
    const int D = in_sizes[0] / N;
    const int S = out_size / D;        // B*G*G
    int gg = S / B;
    int G = 1;
    while (G * G < gg) ++G;

    k_prefix<<<1, 32>>>(bn, B);
    size_t smem = (size_t)(B + 1) * sizeof(int);

    bool fast = (N <= CAP_N) && (S <= CAP_S) && (D == 128) &&
                (B <= 1024) && (G * G == gg) && (S == B * gg);

    if (fast) {
        k_clear<<<(S + 255) / 256, 256>>>(S);
        int nb = (N + 255) / 256;
        k_hist<<<nb, 256, smem>>>(xy, N, G, B);
        k_scan<<<1, 1024>>>(S);
        k_scatter<<<nb, 256, smem>>>(xy, N, G, B);
        k_reduce<<<S, 256>>>(feat, out);   // writes every output element
    } else {
        cudaMemsetAsync(d_out, 0, (size_t)out_size * sizeof(float), 0);
        long long batches = ((long long)N + 31) / 32;
        int blocks = (int)((batches + 7) / 8);
        if (blocks > 65535) blocks = 65535;
        spp_pool_fallback<<<blocks, 256, smem>>>(feat, xy, out, N, D, G, B);
    }
}